// round 5
// baseline (speedup 1.0000x reference)
#include <cuda_runtime.h>
#include <cuda_fp16.h>
#include <cstdint>

#define D_DIM   1024
#define NKB     32            // 1024/32 k-blocks
#define NITER   32
#define STAGES  8
#define BM      128
#define BN      256
#define NPA     64            // 8192/128 row panels
#define NPB     16            // 4096/256 col panels

#define A_KB_BYTES 4096       // 8 mblk x 512B
#define B_KB_BYTES 8192       // 32 nblk x 256B
#define STAGE_BYTES (A_KB_BYTES + B_KB_BYTES)     // 12288
#define SMEM_DYN (1024 + STAGES * STAGE_BYTES)
#define DELTA 5e-3f

__device__ __align__(128) unsigned char g_A[(size_t)NPA * NKB * A_KB_BYTES]; // 8.4 MB
__device__ __align__(128) unsigned char g_B[(size_t)NPB * NKB * B_KB_BYTES]; // 4.2 MB
__device__ unsigned long long g_cands[(size_t)8192 * 256];                    // 16 MB
__device__ float g_einv[8192];
__device__ float g_cinv[4096];
__device__ float g_qsa[8192];   // per-row int8 scale (A)
__device__ float g_qsb[4096];   // per-col int8 scale (B)

// ---------------- PTX helpers ----------------
__device__ __forceinline__ uint32_t smem_u32(const void* p) {
    uint32_t a;
    asm("{ .reg .u64 t; cvta.to.shared.u64 t, %1; cvt.u32.u64 %0, t; }" : "=r"(a) : "l"(p));
    return a;
}
#define MBAR_INIT(a, n) \
    asm volatile("mbarrier.init.shared.b64 [%0], %1;" :: "r"(a), "r"((uint32_t)(n)) : "memory")
#define MBAR_ARRIVE(a) \
    asm volatile("mbarrier.arrive.shared.b64 _, [%0];" :: "r"(a) : "memory")
#define MBAR_EXPECT_TX(a, b) \
    asm volatile("mbarrier.arrive.expect_tx.shared.b64 _, [%0], %1;" :: "r"(a), "r"((uint32_t)(b)) : "memory")
#define MBAR_WAIT(a, ph) do {                                                      \
    uint32_t _m = (a), _p = (ph), _d;                                              \
    asm volatile("{ .reg .pred p; mbarrier.try_wait.parity.acquire.cta.shared::cta.b64 p, [%1], %2; selp.b32 %0,1,0,p; }" \
        : "=r"(_d) : "r"(_m), "r"(_p) : "memory");                                 \
    if (!_d) {                                                                     \
        asm volatile("{ .reg .pred P; L1_%=: mbarrier.try_wait.parity.acquire.cta.shared::cta.b64 P, [%0], %1, 0x989680; @P bra.uni L2_%=; bra.uni L1_%=; L2_%=: }" \
            :: "r"(_m), "r"(_p) : "memory");                                       \
    }                                                                              \
} while (0)

__device__ __forceinline__ void bulk_g2s(uint32_t dst, const void* src,
                                         uint32_t bytes, uint32_t mbar) {
    asm volatile("cp.async.bulk.shared::cluster.global.mbarrier::complete_tx::bytes [%0], [%1], %2, [%3];"
        :: "r"(dst), "l"(src), "r"(bytes), "r"(mbar) : "memory");
}
__device__ __forceinline__ void imma(int* d, const uint32_t* a, const uint32_t* b) {
    asm volatile(
        "mma.sync.aligned.m16n8k32.row.col.s32.s8.s8.s32 "
        "{%0,%1,%2,%3}, {%4,%5,%6,%7}, {%8,%9}, {%0,%1,%2,%3};"
        : "+r"(d[0]), "+r"(d[1]), "+r"(d[2]), "+r"(d[3])
        : "r"(a[0]), "r"(a[1]), "r"(a[2]), "r"(a[3]), "r"(b[0]), "r"(b[1]));
}
__device__ __forceinline__ unsigned long long enc_key(float sim, int col) {
    return ((unsigned long long)__float_as_uint(sim) << 32) |
           (unsigned long long)(0xFFFFFFFFu - (unsigned)col);
}

// ---------------- normalize + per-row int8 quantize + fragment-pack ----------------
__global__ void split_kernel(const float* __restrict__ emb,
                             const float* __restrict__ cen, int B_, int C_) {
    const int row = blockIdx.x;
    const bool isA = row < B_;
    const float* p = isA ? emb + (size_t)row * D_DIM
                         : cen + (size_t)(row - B_) * D_DIM;
    float4 v = reinterpret_cast<const float4*>(p)[threadIdx.x];
    float s = v.x * v.x + v.y * v.y + v.z * v.z + v.w * v.w;
    float ma = fmaxf(fmaxf(fabsf(v.x), fabsf(v.y)), fmaxf(fabsf(v.z), fabsf(v.w)));
#pragma unroll
    for (int m = 16; m >= 1; m >>= 1) {
        s  += __shfl_xor_sync(0xffffffffu, s, m);
        ma = fmaxf(ma, __shfl_xor_sync(0xffffffffu, ma, m));
    }
    __shared__ float ws[8], wm[8];
    __shared__ float s_r127;
    const int w = threadIdx.x >> 5;
    if ((threadIdx.x & 31) == 0) { ws[w] = s; wm[w] = ma; }
    __syncthreads();
    if (threadIdx.x == 0) {
        float t = 0.f, mt = 0.f;
#pragma unroll
        for (int j = 0; j < 8; ++j) { t += ws[j]; mt = fmaxf(mt, wm[j]); }
        const float inv = 1.0f / fmaxf(sqrtf(t), 1e-12f);
        mt = fmaxf(mt, 1e-20f);
        s_r127 = 127.0f / mt;
        const float qs = mt * inv * (1.0f / 127.0f);   // scale for sim reconstruction
        if (isA) { g_einv[row] = inv; g_qsa[row] = qs; }
        else     { g_cinv[row - B_] = inv; g_qsb[row - B_] = qs; }
    }
    __syncthreads();
    const float r127 = s_r127;

    int q[4];
    q[0] = __float2int_rn(v.x * r127);
    q[1] = __float2int_rn(v.y * r127);
    q[2] = __float2int_rn(v.z * r127);
    q[3] = __float2int_rn(v.w * r127);
#pragma unroll
    for (int j = 0; j < 4; ++j) q[j] = max(-127, min(127, q[j]));
    const uint32_t pk = (uint32_t)(q[0] & 0xFF) | ((uint32_t)(q[1] & 0xFF) << 8) |
                        ((uint32_t)(q[2] & 0xFF) << 16) | ((uint32_t)q[3] << 24);

    const int k0 = threadIdx.x * 4;      // 4 consecutive k, one 4B fragment word
    const int kb = k0 >> 5;
    if (isA) {
        const int pnl = row >> 7;
        const int mblk = (row & 127) >> 4;
        const int i = row & 15;
        const int lane = (i & 7) * 4 + ((k0 & 15) >> 2);
        const int reg = (i >> 3) + 2 * ((k0 & 31) >> 4);
        *(uint32_t*)(g_A + ((size_t)(pnl * NKB + kb) * A_KB_BYTES) +
                     (uint32_t)mblk * 512 + lane * 16 + reg * 4) = pk;
    } else {
        const int c = row - B_;
        const int pnl = c >> 8;
        const int nblk = (c & 255) >> 3;
        const int n = c & 7;
        const int lane = n * 4 + ((k0 & 15) >> 2);
        const int reg = (k0 & 31) >> 4;
        *(uint32_t*)(g_B + ((size_t)(pnl * NKB + kb) * B_KB_BYTES) +
                     (uint32_t)nblk * 256 + lane * 8 + reg * 4) = pk;
    }
}

// ---------------- int8 IMMA GEMM + per-(row, 32-col quarter) top-2 ----------------
__global__ void __launch_bounds__(544, 1) gemm_kernel() {
    extern __shared__ __align__(16) unsigned char smem[];
    const uint32_t sbase = smem_u32(smem);
    const int tid = threadIdx.x;
    const int wid = tid >> 5;
    const int lane = tid & 31;

    const uint32_t mb_full  = sbase;            // 8 x 8B
    const uint32_t mb_empty = sbase + 128;      // 8 x 8B
    const uint32_t tiles    = sbase + 1024;

    if (tid == 0) {
#pragma unroll
        for (int s = 0; s < STAGES; ++s) {
            MBAR_INIT(mb_full + s * 8, 1);
            MBAR_INIT(mb_empty + s * 8, 16);    // 16 consumer warps
        }
    }
    __syncthreads();

    if (wid == 16) {
        if (lane == 0) {
            const unsigned char* aP = g_A + (size_t)blockIdx.y * NKB * A_KB_BYTES;
            const unsigned char* bP = g_B + (size_t)blockIdx.x * NKB * B_KB_BYTES;
            for (int kt = 0; kt < NITER; ++kt) {
                const int s = kt & (STAGES - 1);
                MBAR_WAIT(mb_empty + s * 8, 1u ^ ((kt >> 3) & 1));
                MBAR_EXPECT_TX(mb_full + s * 8, STAGE_BYTES);
                const uint32_t st = tiles + s * STAGE_BYTES;
                bulk_g2s(st,        aP + (size_t)kt * A_KB_BYTES, A_KB_BYTES,
                         mb_full + s * 8);
                bulk_g2s(st + A_KB_BYTES, bP + (size_t)kt * B_KB_BYTES, B_KB_BYTES,
                         mb_full + s * 8);
            }
        }
        return;
    }

    const int wm = wid & 1;      // M half (64 rows)
    const int wn = wid >> 1;     // N slice (32 cols), 0..7

    int acc[4][4][4];
#pragma unroll
    for (int mi = 0; mi < 4; ++mi)
#pragma unroll
        for (int ni = 0; ni < 4; ++ni)
#pragma unroll
            for (int q = 0; q < 4; ++q) acc[mi][ni][q] = 0;

    const uint32_t aoff = lane * 16;
    const uint32_t boff = lane * 8;

    for (int kt = 0; kt < NITER; ++kt) {
        const int s = kt & (STAGES - 1);
        MBAR_WAIT(mb_full + s * 8, (kt >> 3) & 1);
        const uint32_t stA = tiles + s * STAGE_BYTES;
        const uint32_t stB = stA + A_KB_BYTES;
        uint32_t a[4][4], b[4][2];
#pragma unroll
        for (int mi = 0; mi < 4; ++mi) {
            const uint32_t ad = stA + (uint32_t)(wm * 4 + mi) * 512 + aoff;
            asm volatile("ld.shared.v4.b32 {%0,%1,%2,%3}, [%4];"
                : "=r"(a[mi][0]), "=r"(a[mi][1]), "=r"(a[mi][2]), "=r"(a[mi][3])
                : "r"(ad));
        }
#pragma unroll
        for (int ni = 0; ni < 4; ++ni) {
            const uint32_t bd = stB + (uint32_t)(wn * 4 + ni) * 256 + boff;
            asm volatile("ld.shared.v2.b32 {%0,%1}, [%2];"
                : "=r"(b[ni][0]), "=r"(b[ni][1]) : "r"(bd));
        }
#pragma unroll
        for (int mi = 0; mi < 4; ++mi)
#pragma unroll
            for (int ni = 0; ni < 4; ++ni)
                imma(acc[mi][ni], a[mi], b[ni]);
        if (lane == 0) MBAR_ARRIVE(mb_empty + s * 8);
    }

    // ---- epilogue: dequant, clip, top-2 per (row, 32-col quarter) ----
    const int rowbase = blockIdx.y * BM + wm * 64;
    const int colbase = blockIdx.x * BN + wn * 32 + (lane & 3) * 2;
    float sb[8];
#pragma unroll
    for (int ni = 0; ni < 4; ++ni) {
        sb[ni * 2 + 0] = g_qsb[colbase + ni * 8 + 0];
        sb[ni * 2 + 1] = g_qsb[colbase + ni * 8 + 1];
    }
#pragma unroll
    for (int mi = 0; mi < 4; ++mi) {
#pragma unroll
        for (int ih = 0; ih < 2; ++ih) {
            const int r = rowbase + mi * 16 + ih * 8 + (lane >> 2);
            const float sa = g_qsa[r];
            unsigned long long k1 = 0ULL, k2 = 0ULL;
#pragma unroll
            for (int ni = 0; ni < 4; ++ni) {
#pragma unroll
                for (int j = 0; j < 2; ++j) {
                    const float sim = fminf(fmaxf(
                        (float)acc[mi][ni][ih * 2 + j] * sa * sb[ni * 2 + j], 0.f), 1.f);
                    const unsigned long long key = enc_key(sim, colbase + ni * 8 + j);
                    if (key > k1) { k2 = k1; k1 = key; }
                    else if (key > k2) { k2 = key; }
                }
            }
#pragma unroll
            for (int m = 1; m <= 2; m <<= 1) {
                const unsigned long long o1 = __shfl_xor_sync(0xffffffffu, k1, m);
                const unsigned long long o2 = __shfl_xor_sync(0xffffffffu, k2, m);
                if (o1 > k1) { k2 = (k1 > o2) ? k1 : o2; k1 = o1; }
                else         { k2 = (k2 > o1) ? k2 : o1; }
            }
            if ((lane & 3) == 0) {
                ulonglong2 kk; kk.x = k1; kk.y = k2;
                *(ulonglong2*)&g_cands[(size_t)r * 256 + blockIdx.x * 16 + wn * 2] = kk;
            }
        }
    }
}

// ---------------- rescore: exact fp32 for all in-window candidates ----------------
__global__ void __launch_bounds__(256) rescore_kernel(
    const float* __restrict__ emb, const float* __restrict__ cen,
    float* __restrict__ out, int B_, int twoout) {
    __shared__ unsigned long long list[8][16];
    __shared__ int lcnt[8];

    const int w = threadIdx.x >> 5;
    const int lane = threadIdx.x & 31;
    const int row = blockIdx.x * 8 + w;
    if (row >= B_) return;

    unsigned long long k[8];
#pragma unroll
    for (int j = 0; j < 8; ++j)
        k[j] = g_cands[(size_t)row * 256 + j * 32 + lane];

    unsigned long long kmax = 0ULL;
#pragma unroll
    for (int j = 0; j < 8; ++j) if (k[j] > kmax) kmax = k[j];
#pragma unroll
    for (int m = 16; m >= 1; m >>= 1) {
        const unsigned long long o = __shfl_xor_sync(0xffffffffu, kmax, m);
        if (o > kmax) kmax = o;
    }
    const float smax = __uint_as_float((unsigned)(kmax >> 32));
    const float th = smax - DELTA;

    if (lane == 0) lcnt[w] = 0;
    __syncwarp();
#pragma unroll
    for (int j = 0; j < 8; ++j) {
        if (__uint_as_float((unsigned)(k[j] >> 32)) >= th) {
            const int pos = atomicAdd(&lcnt[w], 1);
            if (pos < 16) list[w][pos] = k[j];
        }
    }
    __syncwarp();
    const int n = min(lcnt[w], 16);

    float4 e[8];
    const float4* e4 = (const float4*)(emb + (size_t)row * D_DIM);
#pragma unroll
    for (int t = 0; t < 8; ++t) e[t] = e4[t * 32 + lane];
    const float einv = g_einv[row];

    unsigned long long bestk = 0ULL;
    for (int i = 0; i < n; ++i) {
        const unsigned col = 0xFFFFFFFFu - (unsigned)(list[w][i] & 0xFFFFFFFFu);
        const float4* c4 = (const float4*)(cen + (size_t)col * D_DIM);
        float d = 0.f;
#pragma unroll
        for (int t = 0; t < 8; ++t) {
            const float4 cv = c4[t * 32 + lane];
            d += e[t].x * cv.x + e[t].y * cv.y + e[t].z * cv.z + e[t].w * cv.w;
        }
#pragma unroll
        for (int m = 16; m >= 1; m >>= 1) d += __shfl_xor_sync(0xffffffffu, d, m);
        const float sim = fminf(fmaxf(d * einv * g_cinv[col], 0.f), 1.f);
        const unsigned long long key = enc_key(sim, (int)col);
        if (key > bestk) bestk = key;
    }

    if (lane == 0) {
        const float bsim = __uint_as_float((unsigned)(bestk >> 32));
        const unsigned bcol = 0xFFFFFFFFu - (unsigned)(bestk & 0xFFFFFFFFu);
        float nov = sqrtf(fmaxf(1.0f - bsim, 0.0f));
        out[row] = fminf(fmaxf(nov, 0.0f), 1.0f);
        if (twoout) out[B_ + row] = (float)bcol;
    }
}

// ---------------- launch ----------------
extern "C" void kernel_launch(void* const* d_in, const int* in_sizes, int n_in,
                              void* d_out, int out_size) {
    const float* emb = (const float*)d_in[0];
    const float* cen = (const float*)d_in[1];
    const int B_ = in_sizes[0] / D_DIM;   // 8192
    const int C_ = in_sizes[1] / D_DIM;   // 4096

    split_kernel<<<B_ + C_, 256>>>(emb, cen, B_, C_);

    cudaFuncSetAttribute(gemm_kernel,
                         cudaFuncAttributeMaxDynamicSharedMemorySize, SMEM_DYN);
    dim3 grid(C_ / BN, B_ / BM);          // 16 x 64 = 1024 CTAs
    gemm_kernel<<<grid, 544, SMEM_DYN>>>();

    const int twoout = (out_size >= 2 * B_) ? 1 : 0;
    rescore_kernel<<<(B_ + 7) / 8, 256>>>(emb, cen, (float*)d_out, B_, twoout);
}

// round 6
// speedup vs baseline: 2.7777x; 2.7777x over previous
#include <cuda_runtime.h>
#include <cuda_fp16.h>
#include <cstdint>

#define D_DIM   1024
#define NKB     64            // 1024/16 k-blocks
#define NITER   32            // 1024/32
#define STAGES  4
#define BM      128
#define BN      128
#define NPA     64            // 8192/128 row panels
#define NPB     32            // 4096/128 col panels

#define A_KB_BYTES 4096
#define B_KB_BYTES 4096
#define STAGE_BYTES 16384
#define SMEM_DYN (1024 + STAGES * STAGE_BYTES)
#define DELTA 5e-3f

__device__ __align__(128) unsigned char g_A[(size_t)NPA * NKB * A_KB_BYTES]; // 16.8 MB
__device__ __align__(128) unsigned char g_B[(size_t)NPB * NKB * B_KB_BYTES]; // 8.4 MB
__device__ unsigned long long g_cands[(size_t)8192 * 256];                    // 16 MB
__device__ float g_einv[8192];
__device__ float g_cinv[4096];

// ---------------- PTX helpers ----------------
__device__ __forceinline__ uint32_t smem_u32(const void* p) {
    uint32_t a;
    asm("{ .reg .u64 t; cvta.to.shared.u64 t, %1; cvt.u32.u64 %0, t; }" : "=r"(a) : "l"(p));
    return a;
}
#define MBAR_INIT(a, n) \
    asm volatile("mbarrier.init.shared.b64 [%0], %1;" :: "r"(a), "r"((uint32_t)(n)) : "memory")
#define MBAR_ARRIVE(a) \
    asm volatile("mbarrier.arrive.shared.b64 _, [%0];" :: "r"(a) : "memory")
#define MBAR_EXPECT_TX(a, b) \
    asm volatile("mbarrier.arrive.expect_tx.shared.b64 _, [%0], %1;" :: "r"(a), "r"((uint32_t)(b)) : "memory")
#define MBAR_WAIT(a, ph) do {                                                      \
    uint32_t _m = (a), _p = (ph), _d;                                              \
    asm volatile("{ .reg .pred p; mbarrier.try_wait.parity.acquire.cta.shared::cta.b64 p, [%1], %2; selp.b32 %0,1,0,p; }" \
        : "=r"(_d) : "r"(_m), "r"(_p) : "memory");                                 \
    if (!_d) {                                                                     \
        asm volatile("{ .reg .pred P; L1_%=: mbarrier.try_wait.parity.acquire.cta.shared::cta.b64 P, [%0], %1, 0x989680; @P bra.uni L2_%=; bra.uni L1_%=; L2_%=: }" \
            :: "r"(_m), "r"(_p) : "memory");                                       \
    }                                                                              \
} while (0)

__device__ __forceinline__ void bulk_g2s(uint32_t dst, const void* src,
                                         uint32_t bytes, uint32_t mbar) {
    asm volatile("cp.async.bulk.shared::cluster.global.mbarrier::complete_tx::bytes [%0], [%1], %2, [%3];"
        :: "r"(dst), "l"(src), "r"(bytes), "r"(mbar) : "memory");
}
// fp16-accumulate HMMA: D,C are 2 regs (4 halves)
__device__ __forceinline__ void hmma16(uint32_t* d, const uint32_t* a, const uint32_t* b) {
    asm volatile(
        "mma.sync.aligned.m16n8k16.row.col.f16.f16.f16.f16 "
        "{%0,%1}, {%2,%3,%4,%5}, {%6,%7}, {%0,%1};"
        : "+r"(d[0]), "+r"(d[1])
        : "r"(a[0]), "r"(a[1]), "r"(a[2]), "r"(a[3]), "r"(b[0]), "r"(b[1]));
}
__device__ __forceinline__ unsigned long long enc_key(float sim, int col) {
    return ((unsigned long long)__float_as_uint(sim) << 32) |
           (unsigned long long)(0xFFFFFFFFu - (unsigned)col);
}

// ---------------- normalize + fp16 fragment-pack ----------------
__global__ void split_kernel(const float* __restrict__ emb,
                             const float* __restrict__ cen, int B_, int C_) {
    const int row = blockIdx.x;
    const bool isA = row < B_;
    const float* p = isA ? emb + (size_t)row * D_DIM
                         : cen + (size_t)(row - B_) * D_DIM;
    float4 v = reinterpret_cast<const float4*>(p)[threadIdx.x];
    float s = v.x * v.x + v.y * v.y + v.z * v.z + v.w * v.w;
#pragma unroll
    for (int m = 16; m >= 1; m >>= 1) s += __shfl_xor_sync(0xffffffffu, s, m);
    __shared__ float ws[8];
    __shared__ float s_inv;
    if ((threadIdx.x & 31) == 0) ws[threadIdx.x >> 5] = s;
    __syncthreads();
    if (threadIdx.x == 0) {
        float t = 0.f;
#pragma unroll
        for (int w = 0; w < 8; ++w) t += ws[w];
        s_inv = 1.0f / fmaxf(sqrtf(t), 1e-12f);
        if (isA) g_einv[row] = s_inv;
        else     g_cinv[row - B_] = s_inv;
    }
    __syncthreads();
    const float inv = s_inv;

    const float u[4] = {v.x * inv, v.y * inv, v.z * inv, v.w * inv};
    __half h[4];
#pragma unroll
    for (int j = 0; j < 4; ++j) h[j] = __float2half_rn(u[j]);

    const int k0 = threadIdx.x * 4;
#pragma unroll
    for (int pr = 0; pr < 2; ++pr) {
        const int kk = k0 + 2 * pr;
        const int ks = kk >> 4;
        const __half2 hi2 = __halves2half2(h[2 * pr], h[2 * pr + 1]);
        if (isA) {
            const int pnl = row >> 7;
            const int mblk = (row & 127) >> 4;
            const int i = row & 15;
            const int lane = (i & 7) * 4 + ((kk & 7) >> 1);
            const int slot = (i >> 3) + 2 * ((kk & 15) >> 3);
            *(__half2*)(g_A + ((size_t)(pnl * NKB + ks) * A_KB_BYTES) +
                        (uint32_t)mblk * 512 + lane * 16 + slot * 4) = hi2;
        } else {
            const int c = row - B_;
            const int pnl = c >> 7;
            const int nblk = (c & 127) >> 3;
            const int n = c & 7;
            const int lane = n * 4 + ((kk & 7) >> 1);
            const int slot = (kk & 15) >> 3;
            *(__half2*)(g_B + ((size_t)(pnl * NKB + ks) * B_KB_BYTES) +
                        (uint32_t)nblk * 256 + lane * 8 + slot * 4) = hi2;
        }
    }
}

// ---------------- HMMA(fp16-acc) GEMM + per-(row, 32-col quarter) top-2 ----------------
__global__ void __launch_bounds__(288, 2) gemm_kernel() {
    extern __shared__ __align__(16) unsigned char smem[];
    const uint32_t sbase = smem_u32(smem);
    const int tid = threadIdx.x;
    const int wid = tid >> 5;
    const int lane = tid & 31;

    const uint32_t mb_full  = sbase;
    const uint32_t mb_empty = sbase + 64;
    const uint32_t tiles    = sbase + 1024;

    if (tid == 0) {
#pragma unroll
        for (int s = 0; s < STAGES; ++s) {
            MBAR_INIT(mb_full + s * 8, 1);
            MBAR_INIT(mb_empty + s * 8, 8);
        }
    }
    __syncthreads();

    if (wid == 8) {
        if (lane == 0) {
            const unsigned char* aP = g_A + (size_t)blockIdx.y * NKB * A_KB_BYTES;
            const unsigned char* bP = g_B + (size_t)blockIdx.x * NKB * B_KB_BYTES;
            for (int kt = 0; kt < NITER; ++kt) {
                const int s = kt & (STAGES - 1);
                MBAR_WAIT(mb_empty + s * 8, 1u ^ ((kt >> 2) & 1));
                MBAR_EXPECT_TX(mb_full + s * 8, STAGE_BYTES);
                const uint32_t st = tiles + s * STAGE_BYTES;
                bulk_g2s(st,        aP + (size_t)(2 * kt) * A_KB_BYTES, 2 * A_KB_BYTES,
                         mb_full + s * 8);
                bulk_g2s(st + 8192, bP + (size_t)(2 * kt) * B_KB_BYTES, 2 * B_KB_BYTES,
                         mb_full + s * 8);
            }
        }
        return;
    }

    const int wm = wid & 1;
    const int wn = wid >> 1;

    uint32_t acc[4][4][2];
#pragma unroll
    for (int mi = 0; mi < 4; ++mi)
#pragma unroll
        for (int ni = 0; ni < 4; ++ni) { acc[mi][ni][0] = 0u; acc[mi][ni][1] = 0u; }

    const uint32_t aoff = lane * 16;
    const uint32_t boff = lane * 8;

    for (int kt = 0; kt < NITER; ++kt) {
        const int s = kt & (STAGES - 1);
        MBAR_WAIT(mb_full + s * 8, (kt >> 2) & 1);
        const uint32_t stA = tiles + s * STAGE_BYTES;
        const uint32_t stB = stA + 8192;
#pragma unroll
        for (int s16 = 0; s16 < 2; ++s16) {
            uint32_t a[4][4], b[4][2];
#pragma unroll
            for (int mi = 0; mi < 4; ++mi) {
                const uint32_t ad = stA + (uint32_t)(s16 * 8 + wm * 4 + mi) * 512 + aoff;
                asm volatile("ld.shared.v4.b32 {%0,%1,%2,%3}, [%4];"
                    : "=r"(a[mi][0]), "=r"(a[mi][1]), "=r"(a[mi][2]), "=r"(a[mi][3])
                    : "r"(ad));
            }
#pragma unroll
            for (int ni = 0; ni < 4; ++ni) {
                const uint32_t bd = stB + (uint32_t)(s16 * 16 + wn * 4 + ni) * 256 + boff;
                asm volatile("ld.shared.v2.b32 {%0,%1}, [%2];"
                    : "=r"(b[ni][0]), "=r"(b[ni][1]) : "r"(bd));
            }
#pragma unroll
            for (int mi = 0; mi < 4; ++mi)
#pragma unroll
                for (int ni = 0; ni < 4; ++ni)
                    hmma16(acc[mi][ni], a[mi], b[ni]);
        }
        if (lane == 0) MBAR_ARRIVE(mb_empty + s * 8);
    }

    // ---- epilogue: clip, top-2 per (row, 32-col quarter) ----
    const int rowbase = blockIdx.y * BM + wm * 64;
    const int colbase = blockIdx.x * BN + wn * 32 + (lane & 3) * 2;
#pragma unroll
    for (int mi = 0; mi < 4; ++mi) {
#pragma unroll
        for (int ih = 0; ih < 2; ++ih) {   // ih: D reg (row group +0 / +8)
            unsigned long long k1 = 0ULL, k2 = 0ULL;
#pragma unroll
            for (int ni = 0; ni < 4; ++ni) {
                const __half2 hv = *(__half2*)&acc[mi][ni][ih];
                const float s0 = fminf(fmaxf(__low2float(hv), 0.f), 1.f);
                const float s1 = fminf(fmaxf(__high2float(hv), 0.f), 1.f);
                const int c = colbase + ni * 8;
                unsigned long long key = enc_key(s0, c);
                if (key > k1) { k2 = k1; k1 = key; }
                else if (key > k2) { k2 = key; }
                key = enc_key(s1, c + 1);
                if (key > k1) { k2 = k1; k1 = key; }
                else if (key > k2) { k2 = key; }
            }
#pragma unroll
            for (int m = 1; m <= 2; m <<= 1) {
                const unsigned long long o1 = __shfl_xor_sync(0xffffffffu, k1, m);
                const unsigned long long o2 = __shfl_xor_sync(0xffffffffu, k2, m);
                if (o1 > k1) { k2 = (k1 > o2) ? k1 : o2; k1 = o1; }
                else         { k2 = (k2 > o1) ? k2 : o1; }
            }
            if ((lane & 3) == 0) {
                const int r = rowbase + mi * 16 + ih * 8 + (lane >> 2);
                ulonglong2 kk; kk.x = k1; kk.y = k2;
                *(ulonglong2*)&g_cands[(size_t)r * 256 + blockIdx.x * 8 + wn * 2] = kk;
            }
        }
    }
}

// ---------------- rescore: exact fp32 for all in-window candidates ----------------
__global__ void __launch_bounds__(256) rescore_kernel(
    const float* __restrict__ emb, const float* __restrict__ cen,
    float* __restrict__ out, int B_, int twoout) {
    __shared__ unsigned long long list[8][16];
    __shared__ int lcnt[8];

    const int w = threadIdx.x >> 5;
    const int lane = threadIdx.x & 31;
    const int row = blockIdx.x * 8 + w;
    if (row >= B_) return;

    unsigned long long k[8];
#pragma unroll
    for (int j = 0; j < 8; ++j)
        k[j] = g_cands[(size_t)row * 256 + j * 32 + lane];

    unsigned long long kmax = 0ULL;
#pragma unroll
    for (int j = 0; j < 8; ++j) if (k[j] > kmax) kmax = k[j];
#pragma unroll
    for (int m = 16; m >= 1; m >>= 1) {
        const unsigned long long o = __shfl_xor_sync(0xffffffffu, kmax, m);
        if (o > kmax) kmax = o;
    }
    const float smax = __uint_as_float((unsigned)(kmax >> 32));
    const float th = smax - DELTA;

    if (lane == 0) lcnt[w] = 0;
    __syncwarp();
#pragma unroll
    for (int j = 0; j < 8; ++j) {
        if (__uint_as_float((unsigned)(k[j] >> 32)) >= th) {
            const int pos = atomicAdd(&lcnt[w], 1);
            if (pos < 16) list[w][pos] = k[j];
        }
    }
    __syncwarp();
    const int n = min(lcnt[w], 16);

    float4 e[8];
    const float4* e4 = (const float4*)(emb + (size_t)row * D_DIM);
#pragma unroll
    for (int t = 0; t < 8; ++t) e[t] = e4[t * 32 + lane];
    const float einv = g_einv[row];

    unsigned long long bestk = 0ULL;
    for (int i = 0; i < n; ++i) {
        const unsigned col = 0xFFFFFFFFu - (unsigned)(list[w][i] & 0xFFFFFFFFu);
        const float4* c4 = (const float4*)(cen + (size_t)col * D_DIM);
        float d = 0.f;
#pragma unroll
        for (int t = 0; t < 8; ++t) {
            const float4 cv = c4[t * 32 + lane];
            d += e[t].x * cv.x + e[t].y * cv.y + e[t].z * cv.z + e[t].w * cv.w;
        }
#pragma unroll
        for (int m = 16; m >= 1; m >>= 1) d += __shfl_xor_sync(0xffffffffu, d, m);
        const float sim = fminf(fmaxf(d * einv * g_cinv[col], 0.f), 1.f);
        const unsigned long long key = enc_key(sim, (int)col);
        if (key > bestk) bestk = key;
    }

    if (lane == 0) {
        const float bsim = __uint_as_float((unsigned)(bestk >> 32));
        const unsigned bcol = 0xFFFFFFFFu - (unsigned)(bestk & 0xFFFFFFFFu);
        float nov = sqrtf(fmaxf(1.0f - bsim, 0.0f));
        out[row] = fminf(fmaxf(nov, 0.0f), 1.0f);
        if (twoout) out[B_ + row] = (float)bcol;
    }
}

// ---------------- launch ----------------
extern "C" void kernel_launch(void* const* d_in, const int* in_sizes, int n_in,
                              void* d_out, int out_size) {
    const float* emb = (const float*)d_in[0];
    const float* cen = (const float*)d_in[1];
    const int B_ = in_sizes[0] / D_DIM;   // 8192
    const int C_ = in_sizes[1] / D_DIM;   // 4096

    split_kernel<<<B_ + C_, 256>>>(emb, cen, B_, C_);

    cudaFuncSetAttribute(gemm_kernel,
                         cudaFuncAttributeMaxDynamicSharedMemorySize, SMEM_DYN);
    dim3 grid(C_ / BN, B_ / BM);          // 32 x 64 = 2048 CTAs
    gemm_kernel<<<grid, 288, SMEM_DYN>>>();

    const int twoout = (out_size >= 2 * B_) ? 1 : 0;
    rescore_kernel<<<(B_ + 7) / 8, 256>>>(emb, cen, (float*)d_out, B_, twoout);
}

// round 8
// speedup vs baseline: 2.8816x; 1.0374x over previous
#include <cuda_runtime.h>
#include <cuda_fp16.h>
#include <cstdint>

#define D_DIM   1024
#define NKB     64            // 1024/16 k-blocks
#define NITER   32            // 1024/32
#define STAGES  4
#define BM      128
#define BN      128
#define NPA     64            // 8192/128 row panels
#define NPB     32            // 4096/128 col panels

#define A_KB_BYTES 4096
#define B_KB_BYTES 4096
#define STAGE_BYTES 16384
#define SMEM_DYN (1024 + STAGES * STAGE_BYTES)
#define DELTA 5e-3f

__device__ __align__(128) unsigned char g_A[(size_t)NPA * NKB * A_KB_BYTES]; // 16.8 MB
__device__ __align__(128) unsigned char g_B[(size_t)NPB * NKB * B_KB_BYTES]; // 8.4 MB
__device__ unsigned long long g_cands[(size_t)8192 * 256];                    // 16 MB
__device__ float g_einv[8192];
__device__ float g_cinv[4096];

struct __align__(8) H4 { __half2 a, b; };

// ---------------- PTX helpers ----------------
__device__ __forceinline__ uint32_t smem_u32(const void* p) {
    uint32_t a;
    asm("{ .reg .u64 t; cvta.to.shared.u64 t, %1; cvt.u32.u64 %0, t; }" : "=r"(a) : "l"(p));
    return a;
}
#define MBAR_INIT(a, n) \
    asm volatile("mbarrier.init.shared.b64 [%0], %1;" :: "r"(a), "r"((uint32_t)(n)) : "memory")
#define MBAR_ARRIVE(a) \
    asm volatile("mbarrier.arrive.shared.b64 _, [%0];" :: "r"(a) : "memory")
#define MBAR_EXPECT_TX(a, b) \
    asm volatile("mbarrier.arrive.expect_tx.shared.b64 _, [%0], %1;" :: "r"(a), "r"((uint32_t)(b)) : "memory")
#define MBAR_WAIT(a, ph) do {                                                      \
    uint32_t _m = (a), _p = (ph), _d;                                              \
    asm volatile("{ .reg .pred p; mbarrier.try_wait.parity.acquire.cta.shared::cta.b64 p, [%1], %2; selp.b32 %0,1,0,p; }" \
        : "=r"(_d) : "r"(_m), "r"(_p) : "memory");                                 \
    if (!_d) {                                                                     \
        asm volatile("{ .reg .pred P; L1_%=: mbarrier.try_wait.parity.acquire.cta.shared::cta.b64 P, [%0], %1, 0x989680; @P bra.uni L2_%=; bra.uni L1_%=; L2_%=: }" \
            :: "r"(_m), "r"(_p) : "memory");                                       \
    }                                                                              \
} while (0)

__device__ __forceinline__ void bulk_g2s(uint32_t dst, const void* src,
                                         uint32_t bytes, uint32_t mbar) {
    asm volatile("cp.async.bulk.shared::cluster.global.mbarrier::complete_tx::bytes [%0], [%1], %2, [%3];"
        :: "r"(dst), "l"(src), "r"(bytes), "r"(mbar) : "memory");
}
__device__ __forceinline__ void hmma16(uint32_t* d, const uint32_t* a, const uint32_t* b) {
    asm volatile(
        "mma.sync.aligned.m16n8k16.row.col.f16.f16.f16.f16 "
        "{%0,%1}, {%2,%3,%4,%5}, {%6,%7}, {%0,%1};"
        : "+r"(d[0]), "+r"(d[1])
        : "r"(a[0]), "r"(a[1]), "r"(a[2]), "r"(a[3]), "r"(b[0]), "r"(b[1]));
}
__device__ __forceinline__ unsigned long long enc_key(float sim, int col) {
    return ((unsigned long long)__float_as_uint(sim) << 32) |
           (unsigned long long)(0xFFFFFFFFu - (unsigned)col);
}

// ---------------- split: 16 rows/block, warp-per-row norm, staged coalesced writes ----------------
// smem staging: 16 rows x (1024+8) halfs, row stride 2064 B (516 words) -> all
// fragment-gather reads below are bank-conflict-free (bank index == lane).
__global__ void __launch_bounds__(512) split_kernel(const float* __restrict__ emb,
                                                    const float* __restrict__ cen,
                                                    int B_, int C_) {
    __shared__ __align__(16) unsigned char sh[16 * 2064];   // 33 KB
    const int t = threadIdx.x;
    const int w = t >> 5;          // warp = local row 0..15
    const int l = t & 31;

    const int nA = B_ >> 4;        // 512 A-blocks
    const bool isA = (int)blockIdx.x < nA;
    const int g = isA ? blockIdx.x : blockIdx.x - nA;   // 16-row group index
    const int row = g * 16 + w;
    const float* p = (isA ? emb : cen) + (size_t)row * D_DIM;

    // load row (warp-coalesced), accumulate sum of squares
    float4 f[8];
    float s = 0.f;
#pragma unroll
    for (int j = 0; j < 8; ++j) {
        f[j] = ((const float4*)p)[l + 32 * j];
        s += f[j].x * f[j].x + f[j].y * f[j].y + f[j].z * f[j].z + f[j].w * f[j].w;
    }
#pragma unroll
    for (int m = 16; m >= 1; m >>= 1) s += __shfl_xor_sync(0xffffffffu, s, m);
    const float inv = 1.0f / fmaxf(sqrtf(s), 1e-12f);
    if (l == 0) {
        if (isA) g_einv[row] = inv;
        else     g_cinv[row] = inv;
    }

    // normalize, convert, stage: halfs [w][k], k = l*4 + 128*j .. +3
#pragma unroll
    for (int j = 0; j < 8; ++j) {
        H4 hv;
        hv.a = __floats2half2_rn(f[j].x * inv, f[j].y * inv);
        hv.b = __floats2half2_rn(f[j].z * inv, f[j].w * inv);
        *(H4*)(sh + w * 2064 + l * 8 + 256 * j) = hv;
    }
    __syncthreads();

    if (isA) {
        // A fragment chunks: [kb 0..63] of 512B; this block owns mblk of panel pnl
        const int pnl = g >> 3, mblk = g & 7;
        unsigned char* base = g_A + (size_t)pnl * NKB * A_KB_BYTES + mblk * 512 + l * 16;
#pragma unroll
        for (int it = 0; it < 4; ++it) {
            const int kb = it * 16 + w;
            uint32_t v[4];
#pragma unroll
            for (int r = 0; r < 4; ++r) {
                const int i  = (l >> 2) + 8 * (r & 1);
                const int kk = kb * 16 + (l & 3) * 2 + 8 * (r >> 1);
                v[r] = *(const uint32_t*)(sh + i * 2064 + kk * 2);
            }
            *(uint4*)(base + (size_t)kb * A_KB_BYTES) = make_uint4(v[0], v[1], v[2], v[3]);
        }
    } else {
        // B fragment chunks: [kb 0..63] x 2 nblks of 256B
        // BN=128 geometry: panel = g>>3 (8 groups of 16 cols per 128-col panel),
        // local nblk base = (g&7)*2.
        const int pnl = g >> 3;
        const int nb_base = (g & 7) * 2;
        unsigned char* base = g_B + (size_t)pnl * NKB * B_KB_BYTES + l * 8;
#pragma unroll
        for (int it = 0; it < 8; ++it) {
            const int ci = it * 16 + w;          // 0..127
            const int kb = ci >> 1, nloc = ci & 1;
            uint32_t v[2];
#pragma unroll
            for (int s2 = 0; s2 < 2; ++s2) {
                const int i  = nloc * 8 + (l >> 2);
                const int kk = kb * 16 + (l & 3) * 2 + 8 * s2;
                v[s2] = *(const uint32_t*)(sh + i * 2064 + kk * 2);
            }
            *(uint2*)(base + (size_t)kb * B_KB_BYTES + (nb_base + nloc) * 256) =
                make_uint2(v[0], v[1]);
        }
    }
}

// ---------------- HMMA(fp16-acc) GEMM + per-(row, 32-col quarter) top-2 ----------------
__global__ void __launch_bounds__(288, 2) gemm_kernel() {
    extern __shared__ __align__(16) unsigned char smem[];
    const uint32_t sbase = smem_u32(smem);
    const int tid = threadIdx.x;
    const int wid = tid >> 5;
    const int lane = tid & 31;

    const uint32_t mb_full  = sbase;
    const uint32_t mb_empty = sbase + 64;
    const uint32_t tiles    = sbase + 1024;

    if (tid == 0) {
#pragma unroll
        for (int s = 0; s < STAGES; ++s) {
            MBAR_INIT(mb_full + s * 8, 1);
            MBAR_INIT(mb_empty + s * 8, 8);
        }
    }
    __syncthreads();

    if (wid == 8) {
        if (lane == 0) {
            const unsigned char* aP = g_A + (size_t)blockIdx.y * NKB * A_KB_BYTES;
            const unsigned char* bP = g_B + (size_t)blockIdx.x * NKB * B_KB_BYTES;
            for (int kt = 0; kt < NITER; ++kt) {
                const int s = kt & (STAGES - 1);
                MBAR_WAIT(mb_empty + s * 8, 1u ^ ((kt >> 2) & 1));
                MBAR_EXPECT_TX(mb_full + s * 8, STAGE_BYTES);
                const uint32_t st = tiles + s * STAGE_BYTES;
                bulk_g2s(st,        aP + (size_t)(2 * kt) * A_KB_BYTES, 2 * A_KB_BYTES,
                         mb_full + s * 8);
                bulk_g2s(st + 8192, bP + (size_t)(2 * kt) * B_KB_BYTES, 2 * B_KB_BYTES,
                         mb_full + s * 8);
            }
        }
        return;
    }

    const int wm = wid & 1;
    const int wn = wid >> 1;

    uint32_t acc[4][4][2];
#pragma unroll
    for (int mi = 0; mi < 4; ++mi)
#pragma unroll
        for (int ni = 0; ni < 4; ++ni) { acc[mi][ni][0] = 0u; acc[mi][ni][1] = 0u; }

    const uint32_t aoff = lane * 16;
    const uint32_t boff = lane * 8;

    for (int kt = 0; kt < NITER; ++kt) {
        const int s = kt & (STAGES - 1);
        MBAR_WAIT(mb_full + s * 8, (kt >> 2) & 1);
        const uint32_t stA = tiles + s * STAGE_BYTES;
        const uint32_t stB = stA + 8192;
#pragma unroll
        for (int s16 = 0; s16 < 2; ++s16) {
            uint32_t a[4][4], b[4][2];
#pragma unroll
            for (int mi = 0; mi < 4; ++mi) {
                const uint32_t ad = stA + (uint32_t)(s16 * 8 + wm * 4 + mi) * 512 + aoff;
                asm volatile("ld.shared.v4.b32 {%0,%1,%2,%3}, [%4];"
                    : "=r"(a[mi][0]), "=r"(a[mi][1]), "=r"(a[mi][2]), "=r"(a[mi][3])
                    : "r"(ad));
            }
#pragma unroll
            for (int ni = 0; ni < 4; ++ni) {
                const uint32_t bd = stB + (uint32_t)(s16 * 16 + wn * 4 + ni) * 256 + boff;
                asm volatile("ld.shared.v2.b32 {%0,%1}, [%2];"
                    : "=r"(b[ni][0]), "=r"(b[ni][1]) : "r"(bd));
            }
#pragma unroll
            for (int mi = 0; mi < 4; ++mi)
#pragma unroll
                for (int ni = 0; ni < 4; ++ni)
                    hmma16(acc[mi][ni], a[mi], b[ni]);
        }
        if (lane == 0) MBAR_ARRIVE(mb_empty + s * 8);
    }

    // ---- epilogue: clip, top-2 per (row, 32-col quarter) ----
    const int rowbase = blockIdx.y * BM + wm * 64;
    const int colbase = blockIdx.x * BN + wn * 32 + (lane & 3) * 2;
#pragma unroll
    for (int mi = 0; mi < 4; ++mi) {
#pragma unroll
        for (int ih = 0; ih < 2; ++ih) {
            unsigned long long k1 = 0ULL, k2 = 0ULL;
#pragma unroll
            for (int ni = 0; ni < 4; ++ni) {
                const __half2 hv = *(__half2*)&acc[mi][ni][ih];
                const float s0 = fminf(fmaxf(__low2float(hv), 0.f), 1.f);
                const float s1 = fminf(fmaxf(__high2float(hv), 0.f), 1.f);
                const int c = colbase + ni * 8;
                unsigned long long key = enc_key(s0, c);
                if (key > k1) { k2 = k1; k1 = key; }
                else if (key > k2) { k2 = key; }
                key = enc_key(s1, c + 1);
                if (key > k1) { k2 = k1; k1 = key; }
                else if (key > k2) { k2 = key; }
            }
#pragma unroll
            for (int m = 1; m <= 2; m <<= 1) {
                const unsigned long long o1 = __shfl_xor_sync(0xffffffffu, k1, m);
                const unsigned long long o2 = __shfl_xor_sync(0xffffffffu, k2, m);
                if (o1 > k1) { k2 = (k1 > o2) ? k1 : o2; k1 = o1; }
                else         { k2 = (k2 > o1) ? k2 : o1; }
            }
            if ((lane & 3) == 0) {
                const int r = rowbase + mi * 16 + ih * 8 + (lane >> 2);
                ulonglong2 kk; kk.x = k1; kk.y = k2;
                *(ulonglong2*)&g_cands[(size_t)r * 256 + blockIdx.x * 8 + wn * 2] = kk;
            }
        }
    }
}

// ---------------- rescore: exact fp32 for all in-window candidates ----------------
__global__ void __launch_bounds__(256) rescore_kernel(
    const float* __restrict__ emb, const float* __restrict__ cen,
    float* __restrict__ out, int B_, int twoout) {
    __shared__ unsigned long long list[8][16];
    __shared__ int lcnt[8];

    const int w = threadIdx.x >> 5;
    const int lane = threadIdx.x & 31;
    const int row = blockIdx.x * 8 + w;
    if (row >= B_) return;

    unsigned long long k[8];
#pragma unroll
    for (int j = 0; j < 8; ++j)
        k[j] = g_cands[(size_t)row * 256 + j * 32 + lane];

    unsigned long long kmax = 0ULL;
#pragma unroll
    for (int j = 0; j < 8; ++j) if (k[j] > kmax) kmax = k[j];
#pragma unroll
    for (int m = 16; m >= 1; m >>= 1) {
        const unsigned long long o = __shfl_xor_sync(0xffffffffu, kmax, m);
        if (o > kmax) kmax = o;
    }
    const float smax = __uint_as_float((unsigned)(kmax >> 32));
    const float th = smax - DELTA;

    if (lane == 0) lcnt[w] = 0;
    __syncwarp();
#pragma unroll
    for (int j = 0; j < 8; ++j) {
        if (__uint_as_float((unsigned)(k[j] >> 32)) >= th) {
            const int pos = atomicAdd(&lcnt[w], 1);
            if (pos < 16) list[w][pos] = k[j];
        }
    }
    __syncwarp();
    const int n = min(lcnt[w], 16);

    float4 e[8];
    const float4* e4 = (const float4*)(emb + (size_t)row * D_DIM);
#pragma unroll
    for (int t = 0; t < 8; ++t) e[t] = e4[t * 32 + lane];
    const float einv = g_einv[row];

    unsigned long long bestk = 0ULL;
    for (int i = 0; i < n; ++i) {
        const unsigned col = 0xFFFFFFFFu - (unsigned)(list[w][i] & 0xFFFFFFFFu);
        const float4* c4 = (const float4*)(cen + (size_t)col * D_DIM);
        float d = 0.f;
#pragma unroll
        for (int t = 0; t < 8; ++t) {
            const float4 cv = c4[t * 32 + lane];
            d += e[t].x * cv.x + e[t].y * cv.y + e[t].z * cv.z + e[t].w * cv.w;
        }
#pragma unroll
        for (int m = 16; m >= 1; m >>= 1) d += __shfl_xor_sync(0xffffffffu, d, m);
        const float sim = fminf(fmaxf(d * einv * g_cinv[col], 0.f), 1.f);
        const unsigned long long key = enc_key(sim, (int)col);
        if (key > bestk) bestk = key;
    }

    if (lane == 0) {
        const float bsim = __uint_as_float((unsigned)(bestk >> 32));
        const unsigned bcol = 0xFFFFFFFFu - (unsigned)(bestk & 0xFFFFFFFFu);
        float nov = sqrtf(fmaxf(1.0f - bsim, 0.0f));
        out[row] = fminf(fmaxf(nov, 0.0f), 1.0f);
        if (twoout) out[B_ + row] = (float)bcol;
    }
}

// ---------------- launch ----------------
extern "C" void kernel_launch(void* const* d_in, const int* in_sizes, int n_in,
                              void* d_out, int out_size) {
    const float* emb = (const float*)d_in[0];
    const float* cen = (const float*)d_in[1];
    const int B_ = in_sizes[0] / D_DIM;   // 8192
    const int C_ = in_sizes[1] / D_DIM;   // 4096

    split_kernel<<<(B_ + C_) / 16, 512>>>(emb, cen, B_, C_);

    cudaFuncSetAttribute(gemm_kernel,
                         cudaFuncAttributeMaxDynamicSharedMemorySize, SMEM_DYN);
    dim3 grid(C_ / BN, B_ / BM);          // 32 x 64 = 2048 CTAs
    gemm_kernel<<<grid, 288, SMEM_DYN>>>();

    const int twoout = (out_size >= 2 * B_) ? 1 : 0;
    rescore_kernel<<<(B_ + 7) / 8, 256>>>(emb, cen, (float*)d_out, B_, twoout);
}